// round 13
// baseline (speedup 1.0000x reference)
#include <cuda_runtime.h>
#include <cuda_fp16.h>

// Problem constants (fixed by the reference)
#define NN 100000
#define NE 1600000
#define FIN 128
#define FH  128
#define FC  40

#define NI4 (NN / 4)                    // 25000 int4 chunks
#define NE4 (NE / 4)                    // 400000 int4 edge chunks
#define SCAN_BLKS ((NI4 + 255) / 256)   // 98

// packed fp32x2 ops (Blackwell sm_103a; ptxas never emits these from C++)
#define FMA_F32X2(d, a, b, c) \
    asm("fma.rn.f32x2 %0, %1, %2, %3;" : "=l"(d) : "l"(a), "l"(b), "l"(c))
#define PACK_DUP_F32(d, s) \
    asm("mov.b64 %0, {%1, %1};" : "=l"(d) : "f"(s))

// ---------------- device scratch (no allocs allowed) ----------------
// one contiguous zeroed region: [deg_out | deg_in | blk_agg]
__device__ __align__(16) int   g_zeroed[2 * NN + 128];
#define G_DEG_OUT (g_zeroed)
#define G_DEG_IN  (g_zeroed + NN)
#define G_BLK_AGG (g_zeroed + 2 * NN)

__device__ __align__(16) int   g_fill[NN];
__device__ __align__(16) int   g_row_off[NN + 4];
__device__ __align__(16) float g_src_norm[NN];
__device__ __align__(16) float g_dst_norm[NN];
__device__ int   g_csr_src[NE];
__device__ __align__(16) __half g_xw [(size_t)NN * FH];  // x @ W1, fp16
__device__ __align__(16) __half g_hs2[(size_t)NN * FH];  // relu epilogue, fp16
__device__ __align__(16) __half g_hw [(size_t)NN * FC];  // hs2 @ W2, fp16

// ---------------- setup kernels ----------------
__global__ __launch_bounds__(256) void k_hist(const int* __restrict__ src,
                                              const int* __restrict__ dst) {
    int i = blockIdx.x * blockDim.x + threadIdx.x;
    if (i < NE4) {
        int4 s = __ldg((const int4*)src + i);
        int4 d = __ldg((const int4*)dst + i);
        atomicAdd(&G_DEG_OUT[s.x], 1);
        atomicAdd(&G_DEG_OUT[s.y], 1);
        atomicAdd(&G_DEG_OUT[s.z], 1);
        atomicAdd(&G_DEG_OUT[s.w], 1);
        atomicAdd(&G_DEG_IN[d.x], 1);
        atomicAdd(&G_DEG_IN[d.y], 1);
        atomicAdd(&G_DEG_IN[d.z], 1);
        atomicAdd(&G_DEG_IN[d.w], 1);
    }
}

// ---- fused exclusive scan of deg_in -> row_off (+ norms + fill cursor) ----
// grid = 98 blocks, all co-resident (< 148 SMs): each block publishes its
// aggregate, spins for all predecessors, computes its prefix locally.
__global__ __launch_bounds__(256) void k_scan_fused() {
    int t = threadIdx.x;
    int b = blockIdx.x;
    int i4 = b * 256 + t;
    bool ok = i4 < NI4;
    int4 v = make_int4(0, 0, 0, 0);
    if (ok) v = ((const int4*)G_DEG_IN)[i4];
    int tsum = v.x + v.y + v.z + v.w;

    // block total
    int lane = t & 31, w = t >> 5;
    int red = tsum;
#pragma unroll
    for (int d = 16; d; d >>= 1) red += __shfl_down_sync(0xffffffffu, red, d);
    __shared__ int ws[8];
    if (lane == 0) ws[w] = red;
    __syncthreads();
    if (t == 0) {
        int tot = 0;
#pragma unroll
        for (int k = 0; k < 8; k++) tot += ws[k];
        atomicExch(&G_BLK_AGG[b], tot + 1);   // publish (value+1, slot pre-zeroed)
    }

    // gather all 98 aggregates (spin until published)
    __shared__ int sagg[SCAN_BLKS];
    if (t < SCAN_BLKS) {
        int val;
        do { val = atomicAdd(&G_BLK_AGG[t], 0); } while (val == 0);
        sagg[t] = val - 1;
    }
    __syncthreads();

    __shared__ int sbpref;
    if (t == 0) {
        int p = 0;
        for (int k = 0; k < b; k++) p += sagg[k];
        sbpref = p;
    }
    // intra-block exclusive scan of tsum
    int incl = tsum;
#pragma unroll
    for (int d = 1; d < 32; d <<= 1) {
        int u = __shfl_up_sync(0xffffffffu, incl, d);
        if (lane >= d) incl += u;
    }
    __shared__ int wsum[8], woff[8];
    if (lane == 31) wsum[w] = incl;
    __syncthreads();
    if (t < 8) {
        int r = 0;
        for (int k = 0; k < t; k++) r += wsum[k];
        woff[t] = r;
    }
    __syncthreads();

    if (ok) {
        int off = sbpref + woff[w] + (incl - tsum);
        int4 ro;
        ro.x = off;
        ro.y = ro.x + v.x;
        ro.z = ro.y + v.y;
        ro.w = ro.z + v.z;
        ((int4*)g_row_off)[i4] = ro;
        ((int4*)g_fill)[i4]    = ro;
        float4 dn;
        dn.x = rsqrtf((float)max(v.x, 1));
        dn.y = rsqrtf((float)max(v.y, 1));
        dn.z = rsqrtf((float)max(v.z, 1));
        dn.w = rsqrtf((float)max(v.w, 1));
        ((float4*)g_dst_norm)[i4] = dn;
        int4 o = ((const int4*)G_DEG_OUT)[i4];
        float4 sn;
        sn.x = rsqrtf((float)max(o.x, 1));
        sn.y = rsqrtf((float)max(o.y, 1));
        sn.z = rsqrtf((float)max(o.z, 1));
        sn.w = rsqrtf((float)max(o.w, 1));
        ((float4*)g_src_norm)[i4] = sn;
    }
    if (b == 0 && t == 0) g_row_off[NN] = NE;
}

__global__ __launch_bounds__(256) void k_fill(const int* __restrict__ src,
                                              const int* __restrict__ dst) {
    int i = blockIdx.x * blockDim.x + threadIdx.x;
    if (i < NE4) {
        int4 s = __ldg((const int4*)src + i);
        int4 d = __ldg((const int4*)dst + i);
        g_csr_src[atomicAdd(&g_fill[d.x], 1)] = s.x;
        g_csr_src[atomicAdd(&g_fill[d.y], 1)] = s.y;
        g_csr_src[atomicAdd(&g_fill[d.z], 1)] = s.z;
        g_csr_src[atomicAdd(&g_fill[d.w], 1)] = s.w;
    }
}

// ---------------- dense GEMM: Y[M,NC] = X[M,128] @ W[128,NC], fp32x2 packed
template<int NC, int TX, int CPT2, int RPT, typename IT, typename OT>
__global__ __launch_bounds__(256) void k_gemm(const IT* __restrict__ X,
                                              const float* __restrict__ W,
                                              OT* __restrict__ Y) {
    static_assert(TX * CPT2 * 2 == NC, "cols");
    static_assert((256 / TX) * RPT == 128, "rows");
    const int BM = 128, KT = 32;
    __shared__ __align__(16) float sW[KT][NC];
    __shared__ __align__(16) float sX[BM][KT + 1];

    int tid  = threadIdx.x;
    int row0 = blockIdx.x * BM;
    int tx = tid % TX, ty = tid / TX;

    unsigned long long acc[RPT][CPT2];
#pragma unroll
    for (int i = 0; i < RPT; i++)
#pragma unroll
        for (int j = 0; j < CPT2; j++) acc[i][j] = 0ull;

    for (int kt = 0; kt < 128; kt += KT) {
        for (int i = tid; i < KT * NC; i += 256)
            sW[i / NC][i % NC] = W[(size_t)(kt + i / NC) * NC + (i % NC)];
        if constexpr (sizeof(IT) == 2) {
            for (int i = tid; i < BM * (KT / 2); i += 256) {
                int r = i >> 4, c2 = i & 15;
                int gr = row0 + r;
                float2 f = make_float2(0.f, 0.f);
                if (gr < NN) {
                    __half2 h = *reinterpret_cast<const __half2*>(
                        &X[(size_t)gr * 128 + kt + 2 * c2]);
                    f = __half22float2(h);
                }
                sX[r][2 * c2]     = f.x;
                sX[r][2 * c2 + 1] = f.y;
            }
        } else {
            for (int i = tid; i < BM * KT; i += 256) {
                int r = i >> 5, c = i & 31;
                int gr = row0 + r;
                sX[r][c] = (gr < NN) ? (float)X[(size_t)gr * 128 + kt + c] : 0.f;
            }
        }
        __syncthreads();

#pragma unroll 8
        for (int k = 0; k < KT; k++) {
            unsigned long long w2[CPT2];
#pragma unroll
            for (int j = 0; j < CPT2; j++)
                w2[j] = *(const unsigned long long*)&sW[k][tx * CPT2 * 2 + 2 * j];
#pragma unroll
            for (int i = 0; i < RPT; i++) {
                float xv = sX[ty * RPT + i][k];
                unsigned long long xx;
                PACK_DUP_F32(xx, xv);
#pragma unroll
                for (int j = 0; j < CPT2; j++)
                    FMA_F32X2(acc[i][j], xx, w2[j], acc[i][j]);
            }
        }
        __syncthreads();
    }

#pragma unroll
    for (int i = 0; i < RPT; i++) {
        int gr = row0 + ty * RPT + i;
        if (gr < NN) {
#pragma unroll
            for (int j = 0; j < CPT2; j++) {
                float2 f = *reinterpret_cast<float2*>(&acc[i][j]);
                if constexpr (sizeof(OT) == 2) {
                    __half2 h = __float22half2_rn(f);
                    *reinterpret_cast<__half2*>(
                        &Y[(size_t)gr * NC + tx * CPT2 * 2 + 2 * j]) = h;
                } else {
                    *reinterpret_cast<float2*>(
                        &Y[(size_t)gr * NC + tx * CPT2 * 2 + 2 * j]) = f;
                }
            }
        }
    }
}

// ---------------- aggregation: one warp per node (plain loop, R6-style) ----
// hs2 = relu( (sum_e xw[src_e]*src_norm[src_e]) * dst_norm + b1 ) * src_norm
__global__ __launch_bounds__(256) void k_agg128(const __half* __restrict__ Y,
                                                const float* __restrict__ bias) {
    int node = (blockIdx.x * blockDim.x + threadIdx.x) >> 5;
    if (node >= NN) return;
    int lane = threadIdx.x & 31;
    int beg = g_row_off[node], end = g_row_off[node + 1];
    float4 acc = make_float4(0.f, 0.f, 0.f, 0.f);
    for (int e = beg; e < end; e++) {
        int s = __ldg(&g_csr_src[e]);
        float sn = __ldg(&g_src_norm[s]);              // warp-broadcast
        uint2 r = __ldg((const uint2*)(Y + (size_t)s * 128) + lane);
        float2 a = __half22float2(*reinterpret_cast<__half2*>(&r.x));
        float2 b = __half22float2(*reinterpret_cast<__half2*>(&r.y));
        acc.x = fmaf(a.x, sn, acc.x);
        acc.y = fmaf(a.y, sn, acc.y);
        acc.z = fmaf(b.x, sn, acc.z);
        acc.w = fmaf(b.y, sn, acc.w);
    }
    float dn = g_dst_norm[node];
    float ps = g_src_norm[node];
    float4 b = ((const float4*)bias)[lane];
    float4 o;
    o.x = fmaxf(fmaf(acc.x, dn, b.x), 0.f) * ps;
    o.y = fmaxf(fmaf(acc.y, dn, b.y), 0.f) * ps;
    o.z = fmaxf(fmaf(acc.z, dn, b.z), 0.f) * ps;
    o.w = fmaxf(fmaf(acc.w, dn, b.w), 0.f) * ps;
    __half2 h0 = __floats2half2_rn(o.x, o.y);
    __half2 h1 = __floats2half2_rn(o.z, o.w);
    uint2 u;
    u.x = *reinterpret_cast<unsigned*>(&h0);
    u.y = *reinterpret_cast<unsigned*>(&h1);
    ((uint2*)(g_hs2 + (size_t)node * 128))[lane] = u;
}

// out = (sum_e hw[src_e]) * dst_norm + b2 (fp16 rows, 20 half2/row)
__global__ __launch_bounds__(256) void k_agg40(const __half* __restrict__ Y,
                                               const float* __restrict__ bias,
                                               float* __restrict__ out) {
    int node = (blockIdx.x * blockDim.x + threadIdx.x) >> 5;
    if (node >= NN) return;
    int lane = threadIdx.x & 31;
    int beg = g_row_off[node], end = g_row_off[node + 1];
    if (lane >= 20) return;
    float2 acc = make_float2(0.f, 0.f);
    int e = beg;
    for (; e + 2 <= end; e += 2) {
        int s0 = __ldg(&g_csr_src[e]);
        int s1 = __ldg(&g_csr_src[e + 1]);
        float2 v0 = __half22float2(__ldg((const __half2*)(Y + (size_t)s0 * FC) + lane));
        float2 v1 = __half22float2(__ldg((const __half2*)(Y + (size_t)s1 * FC) + lane));
        acc.x += v0.x + v1.x;
        acc.y += v0.y + v1.y;
    }
    if (e < end) {
        int s = __ldg(&g_csr_src[e]);
        float2 v = __half22float2(__ldg((const __half2*)(Y + (size_t)s * FC) + lane));
        acc.x += v.x;
        acc.y += v.y;
    }
    float dn = g_dst_norm[node];
    float2 o;
    o.x = fmaf(acc.x, dn, bias[2 * lane]);
    o.y = fmaf(acc.y, dn, bias[2 * lane + 1]);
    *reinterpret_cast<float2*>(out + (size_t)node * FC + 2 * lane) = o;
}

// ---------------- launch ----------------
extern "C" void kernel_launch(void* const* d_in, const int* in_sizes, int n_in,
                              void* d_out, int out_size) {
    const float* x   = (const float*)d_in[0];
    const float* W1  = (const float*)d_in[1];
    const float* b1  = (const float*)d_in[2];
    const float* W2  = (const float*)d_in[3];
    const float* b2  = (const float*)d_in[4];
    const int*   src = (const int*)  d_in[5];
    const int*   dst = (const int*)  d_in[6];
    float* out = (float*)d_out;

    __half *xw, *hs2, *hw;
    int *zeroed;
    cudaGetSymbolAddress((void**)&xw,     g_xw);
    cudaGetSymbolAddress((void**)&hs2,    g_hs2);
    cudaGetSymbolAddress((void**)&hw,     g_hw);
    cudaGetSymbolAddress((void**)&zeroed, g_zeroed);

    // fork: GEMM1 (independent of graph structure) overlaps the CSR chain
    cudaStream_t s2;
    cudaStreamCreateWithFlags(&s2, cudaStreamNonBlocking);
    cudaEvent_t eFork, eJoin;
    cudaEventCreateWithFlags(&eFork, cudaEventDisableTiming);
    cudaEventCreateWithFlags(&eJoin, cudaEventDisableTiming);

    cudaEventRecord(eFork, 0);
    cudaStreamWaitEvent(s2, eFork, 0);

    k_gemm<128, 16, 4, 8, float, __half><<<(NN + 127) / 128, 256, 0, s2>>>(x, W1, xw);
    cudaEventRecord(eJoin, s2);

    // main stream: CSR + norms (4 ops total)
    cudaMemsetAsync(zeroed, 0, (2 * NN + 128) * sizeof(int), 0);
    k_hist<<<(NE4 + 255) / 256, 256>>>(src, dst);
    k_scan_fused<<<SCAN_BLKS, 256>>>();
    k_fill<<<(NE4 + 255) / 256, 256>>>(src, dst);

    cudaStreamWaitEvent(0, eJoin, 0);

    k_agg128<<<(NN * 32 + 255) / 256, 256>>>(xw, b1);
    k_gemm<40, 4, 5, 2, __half, __half><<<(NN + 127) / 128, 256>>>(hs2, W2, hw);
    k_agg40<<<(NN * 32 + 255) / 256, 256>>>(hw, b2, out);

    cudaEventDestroy(eFork);
    cudaEventDestroy(eJoin);
    cudaStreamDestroy(s2);
}

// round 14
// speedup vs baseline: 1.0056x; 1.0056x over previous
#include <cuda_runtime.h>
#include <cuda_fp16.h>

// Problem constants (fixed by the reference)
#define NN 100000
#define NE 1600000
#define FIN 128
#define FH  128
#define FC  40

#define NI4 (NN / 4)                    // 25000 int4 chunks
#define NE4 (NE / 4)                    // 400000 int4 edge chunks
#define SCAN_BLKS ((NI4 + 255) / 256)   // 98

// packed fp32x2 ops (Blackwell sm_103a; ptxas never emits these from C++)
#define FMA_F32X2(d, a, b, c) \
    asm("fma.rn.f32x2 %0, %1, %2, %3;" : "=l"(d) : "l"(a), "l"(b), "l"(c))
#define PACK_DUP_F32(d, s) \
    asm("mov.b64 %0, {%1, %1};" : "=l"(d) : "f"(s))

// ---------------- device scratch (no allocs allowed) ----------------
// one contiguous zeroed region: [deg_out | deg_in | blk_agg]
__device__ __align__(16) int   g_zeroed[2 * NN + 128];
#define G_DEG_OUT (g_zeroed)
#define G_DEG_IN  (g_zeroed + NN)
#define G_BLK_AGG (g_zeroed + 2 * NN)

__device__ __align__(16) int   g_fill[NN];
__device__ __align__(16) int   g_row_off[NN + 4];
__device__ __align__(16) float g_src_norm[NN];
__device__ __align__(16) float g_dst_norm[NN];
__device__ int   g_csr_src[NE];
__device__ __align__(16) __half g_xw [(size_t)NN * FH];  // x @ W1, fp16
__device__ __align__(16) __half g_hs2[(size_t)NN * FH];  // relu epilogue, fp16
__device__ __align__(16) __half g_hw [(size_t)NN * FC];  // hs2 @ W2, fp16

// ---------------- setup kernels ----------------
__global__ __launch_bounds__(256) void k_hist(const int* __restrict__ src,
                                              const int* __restrict__ dst) {
    int i = blockIdx.x * blockDim.x + threadIdx.x;
    if (i < NE4) {
        int4 s = __ldg((const int4*)src + i);
        int4 d = __ldg((const int4*)dst + i);
        atomicAdd(&G_DEG_OUT[s.x], 1);
        atomicAdd(&G_DEG_OUT[s.y], 1);
        atomicAdd(&G_DEG_OUT[s.z], 1);
        atomicAdd(&G_DEG_OUT[s.w], 1);
        atomicAdd(&G_DEG_IN[d.x], 1);
        atomicAdd(&G_DEG_IN[d.y], 1);
        atomicAdd(&G_DEG_IN[d.z], 1);
        atomicAdd(&G_DEG_IN[d.w], 1);
    }
}

// ---- fused exclusive scan of deg_in -> row_off (+ norms + fill cursor) ----
// grid = 98 blocks, all co-resident (< 148 SMs): each block publishes its
// aggregate, spins for all predecessors, computes its prefix locally.
__global__ __launch_bounds__(256) void k_scan_fused() {
    int t = threadIdx.x;
    int b = blockIdx.x;
    int i4 = b * 256 + t;
    bool ok = i4 < NI4;
    int4 v = make_int4(0, 0, 0, 0);
    if (ok) v = ((const int4*)G_DEG_IN)[i4];
    int tsum = v.x + v.y + v.z + v.w;

    // block total
    int lane = t & 31, w = t >> 5;
    int red = tsum;
#pragma unroll
    for (int d = 16; d; d >>= 1) red += __shfl_down_sync(0xffffffffu, red, d);
    __shared__ int ws[8];
    if (lane == 0) ws[w] = red;
    __syncthreads();
    if (t == 0) {
        int tot = 0;
#pragma unroll
        for (int k = 0; k < 8; k++) tot += ws[k];
        atomicExch(&G_BLK_AGG[b], tot + 1);   // publish (value+1, slot pre-zeroed)
    }

    // gather all 98 aggregates (spin until published)
    __shared__ int sagg[SCAN_BLKS];
    if (t < SCAN_BLKS) {
        int val;
        do { val = atomicAdd(&G_BLK_AGG[t], 0); } while (val == 0);
        sagg[t] = val - 1;
    }
    __syncthreads();

    __shared__ int sbpref;
    if (t == 0) {
        int p = 0;
        for (int k = 0; k < b; k++) p += sagg[k];
        sbpref = p;
    }
    // intra-block exclusive scan of tsum
    int incl = tsum;
#pragma unroll
    for (int d = 1; d < 32; d <<= 1) {
        int u = __shfl_up_sync(0xffffffffu, incl, d);
        if (lane >= d) incl += u;
    }
    __shared__ int wsum[8], woff[8];
    if (lane == 31) wsum[w] = incl;
    __syncthreads();
    if (t < 8) {
        int r = 0;
        for (int k = 0; k < t; k++) r += wsum[k];
        woff[t] = r;
    }
    __syncthreads();

    if (ok) {
        int off = sbpref + woff[w] + (incl - tsum);
        int4 ro;
        ro.x = off;
        ro.y = ro.x + v.x;
        ro.z = ro.y + v.y;
        ro.w = ro.z + v.z;
        ((int4*)g_row_off)[i4] = ro;
        ((int4*)g_fill)[i4]    = ro;
        float4 dn;
        dn.x = rsqrtf((float)max(v.x, 1));
        dn.y = rsqrtf((float)max(v.y, 1));
        dn.z = rsqrtf((float)max(v.z, 1));
        dn.w = rsqrtf((float)max(v.w, 1));
        ((float4*)g_dst_norm)[i4] = dn;
        int4 o = ((const int4*)G_DEG_OUT)[i4];
        float4 sn;
        sn.x = rsqrtf((float)max(o.x, 1));
        sn.y = rsqrtf((float)max(o.y, 1));
        sn.z = rsqrtf((float)max(o.z, 1));
        sn.w = rsqrtf((float)max(o.w, 1));
        ((float4*)g_src_norm)[i4] = sn;
    }
    if (b == 0 && t == 0) g_row_off[NN] = NE;
}

__global__ __launch_bounds__(256) void k_fill(const int* __restrict__ src,
                                              const int* __restrict__ dst) {
    int i = blockIdx.x * blockDim.x + threadIdx.x;
    if (i < NE4) {
        int4 s = __ldg((const int4*)src + i);
        int4 d = __ldg((const int4*)dst + i);
        g_csr_src[atomicAdd(&g_fill[d.x], 1)] = s.x;
        g_csr_src[atomicAdd(&g_fill[d.y], 1)] = s.y;
        g_csr_src[atomicAdd(&g_fill[d.z], 1)] = s.z;
        g_csr_src[atomicAdd(&g_fill[d.w], 1)] = s.w;
    }
}

// ---------------- dense GEMM: Y[M,NC] = X[M,128] @ W[128,NC], fp32x2 packed
template<int NC, int TX, int CPT2, int RPT, typename IT, typename OT>
__global__ __launch_bounds__(256) void k_gemm(const IT* __restrict__ X,
                                              const float* __restrict__ W,
                                              OT* __restrict__ Y) {
    static_assert(TX * CPT2 * 2 == NC, "cols");
    static_assert((256 / TX) * RPT == 128, "rows");
    const int BM = 128, KT = 32;
    __shared__ __align__(16) float sW[KT][NC];
    __shared__ __align__(16) float sX[BM][KT + 1];

    int tid  = threadIdx.x;
    int row0 = blockIdx.x * BM;
    int tx = tid % TX, ty = tid / TX;

    unsigned long long acc[RPT][CPT2];
#pragma unroll
    for (int i = 0; i < RPT; i++)
#pragma unroll
        for (int j = 0; j < CPT2; j++) acc[i][j] = 0ull;

    for (int kt = 0; kt < 128; kt += KT) {
        for (int i = tid; i < KT * NC; i += 256)
            sW[i / NC][i % NC] = W[(size_t)(kt + i / NC) * NC + (i % NC)];
        if constexpr (sizeof(IT) == 2) {
            for (int i = tid; i < BM * (KT / 2); i += 256) {
                int r = i >> 4, c2 = i & 15;
                int gr = row0 + r;
                float2 f = make_float2(0.f, 0.f);
                if (gr < NN) {
                    __half2 h = *reinterpret_cast<const __half2*>(
                        &X[(size_t)gr * 128 + kt + 2 * c2]);
                    f = __half22float2(h);
                }
                sX[r][2 * c2]     = f.x;
                sX[r][2 * c2 + 1] = f.y;
            }
        } else {
            for (int i = tid; i < BM * KT; i += 256) {
                int r = i >> 5, c = i & 31;
                int gr = row0 + r;
                sX[r][c] = (gr < NN) ? (float)X[(size_t)gr * 128 + kt + c] : 0.f;
            }
        }
        __syncthreads();

#pragma unroll 8
        for (int k = 0; k < KT; k++) {
            unsigned long long w2[CPT2];
#pragma unroll
            for (int j = 0; j < CPT2; j++)
                w2[j] = *(const unsigned long long*)&sW[k][tx * CPT2 * 2 + 2 * j];
#pragma unroll
            for (int i = 0; i < RPT; i++) {
                float xv = sX[ty * RPT + i][k];
                unsigned long long xx;
                PACK_DUP_F32(xx, xv);
#pragma unroll
                for (int j = 0; j < CPT2; j++)
                    FMA_F32X2(acc[i][j], xx, w2[j], acc[i][j]);
            }
        }
        __syncthreads();
    }

#pragma unroll
    for (int i = 0; i < RPT; i++) {
        int gr = row0 + ty * RPT + i;
        if (gr < NN) {
#pragma unroll
            for (int j = 0; j < CPT2; j++) {
                float2 f = *reinterpret_cast<float2*>(&acc[i][j]);
                if constexpr (sizeof(OT) == 2) {
                    __half2 h = __float22half2_rn(f);
                    *reinterpret_cast<__half2*>(
                        &Y[(size_t)gr * NC + tx * CPT2 * 2 + 2 * j]) = h;
                } else {
                    *reinterpret_cast<float2*>(
                        &Y[(size_t)gr * NC + tx * CPT2 * 2 + 2 * j]) = f;
                }
            }
        }
    }
}

// ---------------- aggregation: one warp per node (plain loop, R6-style) ----
// hs2 = relu( (sum_e xw[src_e]*src_norm[src_e]) * dst_norm + b1 ) * src_norm
__global__ __launch_bounds__(256) void k_agg128(const __half* __restrict__ Y,
                                                const float* __restrict__ bias) {
    int node = (blockIdx.x * blockDim.x + threadIdx.x) >> 5;
    if (node >= NN) return;
    int lane = threadIdx.x & 31;
    int beg = g_row_off[node], end = g_row_off[node + 1];
    float4 acc = make_float4(0.f, 0.f, 0.f, 0.f);
    for (int e = beg; e < end; e++) {
        int s = __ldg(&g_csr_src[e]);
        float sn = __ldg(&g_src_norm[s]);              // warp-broadcast
        uint2 r = __ldg((const uint2*)(Y + (size_t)s * 128) + lane);
        float2 a = __half22float2(*reinterpret_cast<__half2*>(&r.x));
        float2 b = __half22float2(*reinterpret_cast<__half2*>(&r.y));
        acc.x = fmaf(a.x, sn, acc.x);
        acc.y = fmaf(a.y, sn, acc.y);
        acc.z = fmaf(b.x, sn, acc.z);
        acc.w = fmaf(b.y, sn, acc.w);
    }
    float dn = g_dst_norm[node];
    float ps = g_src_norm[node];
    float4 b = ((const float4*)bias)[lane];
    float4 o;
    o.x = fmaxf(fmaf(acc.x, dn, b.x), 0.f) * ps;
    o.y = fmaxf(fmaf(acc.y, dn, b.y), 0.f) * ps;
    o.z = fmaxf(fmaf(acc.z, dn, b.z), 0.f) * ps;
    o.w = fmaxf(fmaf(acc.w, dn, b.w), 0.f) * ps;
    __half2 h0 = __floats2half2_rn(o.x, o.y);
    __half2 h1 = __floats2half2_rn(o.z, o.w);
    uint2 u;
    u.x = *reinterpret_cast<unsigned*>(&h0);
    u.y = *reinterpret_cast<unsigned*>(&h1);
    ((uint2*)(g_hs2 + (size_t)node * 128))[lane] = u;
}

// out = (sum_e hw[src_e]) * dst_norm + b2 (fp16 rows, 20 half2/row)
__global__ __launch_bounds__(256) void k_agg40(const __half* __restrict__ Y,
                                               const float* __restrict__ bias,
                                               float* __restrict__ out) {
    int node = (blockIdx.x * blockDim.x + threadIdx.x) >> 5;
    if (node >= NN) return;
    int lane = threadIdx.x & 31;
    int beg = g_row_off[node], end = g_row_off[node + 1];
    if (lane >= 20) return;
    float2 acc = make_float2(0.f, 0.f);
    int e = beg;
    for (; e + 2 <= end; e += 2) {
        int s0 = __ldg(&g_csr_src[e]);
        int s1 = __ldg(&g_csr_src[e + 1]);
        float2 v0 = __half22float2(__ldg((const __half2*)(Y + (size_t)s0 * FC) + lane));
        float2 v1 = __half22float2(__ldg((const __half2*)(Y + (size_t)s1 * FC) + lane));
        acc.x += v0.x + v1.x;
        acc.y += v0.y + v1.y;
    }
    if (e < end) {
        int s = __ldg(&g_csr_src[e]);
        float2 v = __half22float2(__ldg((const __half2*)(Y + (size_t)s * FC) + lane));
        acc.x += v.x;
        acc.y += v.y;
    }
    float dn = g_dst_norm[node];
    float2 o;
    o.x = fmaf(acc.x, dn, bias[2 * lane]);
    o.y = fmaf(acc.y, dn, bias[2 * lane + 1]);
    *reinterpret_cast<float2*>(out + (size_t)node * FC + 2 * lane) = o;
}

// ---------------- launch ----------------
extern "C" void kernel_launch(void* const* d_in, const int* in_sizes, int n_in,
                              void* d_out, int out_size) {
    const float* x   = (const float*)d_in[0];
    const float* W1  = (const float*)d_in[1];
    const float* b1  = (const float*)d_in[2];
    const float* W2  = (const float*)d_in[3];
    const float* b2  = (const float*)d_in[4];
    const int*   src = (const int*)  d_in[5];
    const int*   dst = (const int*)  d_in[6];
    float* out = (float*)d_out;

    __half *xw, *hs2, *hw;
    int *zeroed;
    cudaGetSymbolAddress((void**)&xw,     g_xw);
    cudaGetSymbolAddress((void**)&hs2,    g_hs2);
    cudaGetSymbolAddress((void**)&hw,     g_hw);
    cudaGetSymbolAddress((void**)&zeroed, g_zeroed);

    // fork: GEMM1 (independent of graph structure) overlaps the CSR chain
    cudaStream_t s2;
    cudaStreamCreateWithFlags(&s2, cudaStreamNonBlocking);
    cudaEvent_t eFork, eJoin;
    cudaEventCreateWithFlags(&eFork, cudaEventDisableTiming);
    cudaEventCreateWithFlags(&eJoin, cudaEventDisableTiming);

    cudaEventRecord(eFork, 0);
    cudaStreamWaitEvent(s2, eFork, 0);

    k_gemm<128, 16, 4, 8, float, __half><<<(NN + 127) / 128, 256, 0, s2>>>(x, W1, xw);
    cudaEventRecord(eJoin, s2);

    // main stream: CSR + norms (4 ops total)
    cudaMemsetAsync(zeroed, 0, (2 * NN + 128) * sizeof(int), 0);
    k_hist<<<(NE4 + 255) / 256, 256>>>(src, dst);
    k_scan_fused<<<SCAN_BLKS, 256>>>();
    k_fill<<<(NE4 + 255) / 256, 256>>>(src, dst);

    cudaStreamWaitEvent(0, eJoin, 0);

    k_agg128<<<(NN * 32 + 255) / 256, 256>>>(xw, b1);
    k_gemm<40, 4, 5, 2, __half, __half><<<(NN + 127) / 128, 256>>>(hs2, W2, hw);
    k_agg40<<<(NN * 32 + 255) / 256, 256>>>(hw, b2, out);

    cudaEventDestroy(eFork);
    cudaEventDestroy(eJoin);
    cudaStreamDestroy(s2);
}